// round 11
// baseline (speedup 1.0000x reference)
#include <cuda_runtime.h>
#include <cstdint>

#define NQ   22
#define DIM  (1u << NQ)     // 4194304 elements per component

// ---- tiny diagonal split tables (device globals, no allocation) ----
// diag[b] = dLo[b&2047] + dHi[b>>11] + sum_{h set in (b>>11)} R[h][b&2047]
__device__ float g_dLo[2048];
__device__ float g_dHi[2048];
__device__ float g_R[11][2048];

__device__ __forceinline__ void add4(float4& a, const float4 b) {
    a.x += b.x; a.y += b.y; a.z += b.z; a.w += b.w;
}

__device__ __forceinline__ uint32_t smem_u32(const void* p) {
    uint32_t a;
    asm("{ .reg .u64 t; cvta.to.shared.u64 t, %1; cvt.u32.u64 %0, t; }"
        : "=r"(a) : "l"(p));
    return a;
}
__device__ __forceinline__ void cpasync16(uint32_t s, const void* g) {
    asm volatile("cp.async.cg.shared.global [%0], [%1], 16;" :: "r"(s), "l"(g));
}
#define CP_COMMIT() asm volatile("cp.async.commit_group;")
#define CP_WAIT0()  asm volatile("cp.async.wait_group 0;")

// ---------------------------------------------------------------------------
// Tables kernel — BRANCH-FREE. Bits become floats; every conditional add
// becomes an FMA. No divergence, short chains via split accumulators.
// ---------------------------------------------------------------------------
__global__ void __launch_bounds__(256)
tables_kernel(const float* __restrict__ U, const float* __restrict__ detune)
{
    __shared__ float sU[NQ * NQ + 1];
    for (int i = threadIdx.x; i < NQ * NQ; i += 256) sU[i] = U[i];
    if (threadIdx.x == 0) sU[NQ * NQ] = detune[0];
    __syncthreads();
    const float det = sU[NQ * NQ];
    const int t = blockIdx.x * 256 + threadIdx.x;   // 0..2047

    float b[11];
#pragma unroll
    for (int q = 0; q < 11; q++) b[q] = (float)((t >> q) & 1);

    // dLo: sum over p of b[p] * (-det + sum_{q<p} b[q]*U[(21-p)*22+(21-q)])
    float dlo0 = 0.f, dlo1 = 0.f;
#pragma unroll
    for (int p = 0; p < 11; p++) {
        float rs = -det;
#pragma unroll
        for (int q = 0; q < p; q++)
            rs = fmaf(b[q], sU[(21 - p) * NQ + (21 - q)], rs);
        if (p & 1) dlo1 = fmaf(b[p], rs, dlo1);
        else       dlo0 = fmaf(b[p], rs, dlo0);
    }
    g_dLo[t] = dlo0 + dlo1;

    // dHi: hi bit h -> qubit row (10-h)
    float dhi0 = 0.f, dhi1 = 0.f;
#pragma unroll
    for (int h = 0; h < 11; h++) {
        float rs = -det;
#pragma unroll
        for (int h2 = 0; h2 < h; h2++)
            rs = fmaf(b[h2], sU[(10 - h) * NQ + (10 - h2)], rs);
        if (h & 1) dhi1 = fmaf(b[h], rs, dhi1);
        else       dhi0 = fmaf(b[h], rs, dhi0);
    }
    g_dHi[t] = dhi0 + dhi1;

    // R[h][t] = sum_q b[q] * U[(10-h)*22 + (21-q)]
#pragma unroll
    for (int h = 0; h < 11; h++) {
        float r0 = 0.f, r1 = 0.f;
#pragma unroll
        for (int q = 0; q < 11; q += 2)
            r0 = fmaf(b[q], sU[(10 - h) * NQ + (21 - q)], r0);
#pragma unroll
        for (int q = 1; q < 11; q += 2)
            r1 = fmaf(b[q], sU[(10 - h) * NQ + (21 - q)], r1);
        g_R[h][t] = r0 + r1;
    }
}

// ---------------------------------------------------------------------------
// K1: low bits 0..13 (14 X-neighbors) + FULL diagonal; writes
//   out = c*acc_low + diag .* psi.
//   Component-split (blockIdx.y). Tile = 16384 consecutive elems = 64KB =
//   4096 f4. 512 threads, 8 f4/thread: G = tid + k*512 (k = elem bits 11..13).
//   bits 0..1  : in-float4 swaps
//   bits 2..10 : 9 smem XOR dirs (G bits 0..8 = tid)
//   bits 11..13: register dirs k^1, k^2, k^4
//   diag: per-thread lo f4 is FIXED across k (lo4 = tid*4) ->
//     D0 = dLo[lo4] + CTA-masked R rows 3..10; R0/R1 in regs; R2 folded at
//     k==4; dHi[(bx<<3)|k] uniform scalar per k.
// ---------------------------------------------------------------------------
__global__ void __launch_bounds__(512, 2)
k1_low_kernel(const float* __restrict__ sr, const float* __restrict__ si,
              const float* __restrict__ rabi, float* __restrict__ out)
{
    extern __shared__ float4 sv[];     // 4096 f4 = 64KB (one component)
    const uint32_t sb = smem_u32(sv);
    const int tid = threadIdx.x;
    const int bx = blockIdx.x;                       // elem bits 14..21
    const int comp = blockIdx.y;
    const float4* g4 = (const float4*)(comp ? si : sr);
    float4* o4 = (float4*)(out + (unsigned)comp * DIM);
    const unsigned gbase = (unsigned)bx << 12;       // f4-group base

#pragma unroll
    for (int j = 0; j < 8; j++) {
        const int idx = tid + j * 512;
        cpasync16(sb + idx * 16, g4 + gbase + idx);
    }
    CP_COMMIT();
    const float c = 0.5f * __ldg(rabi);

    // ---- diag staging: all L1/L2 loads overlap the cp.async fill ----
    const int lo4 = tid << 2;                        // elem bits 0..10, f4 base
    float4 D0 = __ldg((const float4*)&g_dLo[lo4]);
#pragma unroll
    for (int t = 0; t < 8; t++)
        if ((bx >> t) & 1) add4(D0, __ldg((const float4*)&g_R[t + 3][lo4]));
    const float4 R0 = __ldg((const float4*)&g_R[0][lo4]);
    const float4 R1 = __ldg((const float4*)&g_R[1][lo4]);

    CP_WAIT0();
    __syncthreads();

    float4 v[8];
#pragma unroll
    for (int k = 0; k < 8; k++) v[k] = sv[tid + k * 512];

#pragma unroll
    for (int k = 0; k < 8; k++) {
        if (k == 4) add4(D0, __ldg((const float4*)&g_R[2][lo4]));  // fold R2
        const int G = tid + k * 512;
        const float4 s = v[k];

        // bits 0..1 (in-float4) + register dirs (bits 11..13)
        float4 a = make_float4(s.y + s.z, s.x + s.w, s.w + s.x, s.z + s.y);
        add4(a, v[k ^ 1]);
        add4(a, v[k ^ 2]);
        add4(a, v[k ^ 4]);

        // 9 smem dirs (bits 2..10), two waves to bound live temps
        float4 t0 = sv[G ^ 1],  t1 = sv[G ^ 2],  t2 = sv[G ^ 4];
        float4 t3 = sv[G ^ 8];
        add4(t0, t1); add4(t2, t3);
        add4(a, t0);  add4(a, t2);

        float4 u0 = sv[G ^ 16],  u1 = sv[G ^ 32],  u2 = sv[G ^ 64];
        float4 u3 = sv[G ^ 128], u4 = sv[G ^ 256];
        add4(u0, u1); add4(u2, u3);
        add4(u0, u2); add4(u4, a);
        add4(u4, u0);

        // diagonal weight (k compile-time -> predicates are free)
        float4 W = D0;
        if (k & 1) add4(W, R0);
        if (k & 2) add4(W, R1);
        const float dh = __ldg(&g_dHi[((unsigned)bx << 3) | k]);
        W.x += dh; W.y += dh; W.z += dh; W.w += dh;

        float4 o;
        o.x = fmaf(c, u4.x, W.x * s.x);
        o.y = fmaf(c, u4.y, W.y * s.y);
        o.z = fmaf(c, u4.z, W.z * s.z);
        o.w = fmaf(c, u4.w, W.w * s.w);
        o4[gbase + G] = o;
    }
}

// ---------------------------------------------------------------------------
// K2: high bits 14..21 (8 X-neighbors), diag-free RMW: out += c*acc.
//   Component-split (blockIdx.y). blockIdx.x = b21<<9 | mid, mid = elem bits
//   5..13 (512), b21 = elem bit 21 (tile-fixed).
//   Tile = 128 combos (elem bits 14..20) x 32-elem rows (128B) = 16KB =
//   1024 f4. 512 threads, 2 f4/thread: idx = tid + k*512.
//   bits 14..19: 6 smem XOR dirs; bit 20: reg dir k^1;
//   bit 21: coalesced GLOBAL dir (gG ^ 1<<19).
//   o and bit-21 neighbors prefetched before the fill wait (full MLP).
// ---------------------------------------------------------------------------
__global__ void __launch_bounds__(512, 3)
k2_high_kernel(const float* __restrict__ sr, const float* __restrict__ si,
               const float* __restrict__ rabi, float* __restrict__ out)
{
    extern __shared__ float4 sv[];     // 1024 f4 = 16KB (one component)
    const uint32_t sb = smem_u32(sv);
    const int tid = threadIdx.x;
    const int comp = blockIdx.y;
    const unsigned mid = blockIdx.x & 511u;          // elem bits 5..13
    const unsigned b21 = blockIdx.x >> 9;            // elem bit 21
    const float4* g4 = (const float4*)(comp ? si : sr);
    float4* o4 = (float4*)(out + (unsigned)comp * DIM);

    const unsigned gG0 = (b21 << 19) + ((unsigned)(tid >> 3) << 12) + (mid << 3) + (tid & 7);
    const unsigned gG1 = gG0 + (64u << 12);          // idx + 512 -> c7 += 64

#pragma unroll
    for (int j = 0; j < 2; j++) {
        const int idx = tid + j * 512;
        const unsigned gG = j ? gG1 : gG0;
        cpasync16(sb + idx * 16, g4 + gG);
    }
    CP_COMMIT();
    const float c = 0.5f * __ldg(rabi);

    // prefetch RMW targets + bit-21 global neighbors behind the fill
    float4 o0 = o4[gG0];
    float4 o1 = o4[gG1];
    float4 n0 = __ldg(&g4[gG0 ^ (1u << 19)]);
    float4 n1 = __ldg(&g4[gG1 ^ (1u << 19)]);

    CP_WAIT0();
    __syncthreads();

    float4 v0 = sv[tid];
    float4 v1 = sv[tid + 512];

    // ---- k = 0 ----
    {
        const int idx = tid;
        float4 t0 = sv[idx ^ 8],   t1 = sv[idx ^ 16],  t2 = sv[idx ^ 32];
        float4 t3 = sv[idx ^ 64],  t4 = sv[idx ^ 128], t5 = sv[idx ^ 256];
        add4(t0, t1); add4(t2, t3); add4(t4, t5);
        add4(t0, v1);                   // reg dir (bit 20)
        add4(t2, n0);                   // global dir (bit 21)
        add4(t0, t2); add4(t0, t4);
        o0.x = fmaf(c, t0.x, o0.x);
        o0.y = fmaf(c, t0.y, o0.y);
        o0.z = fmaf(c, t0.z, o0.z);
        o0.w = fmaf(c, t0.w, o0.w);
        o4[gG0] = o0;
    }
    // ---- k = 1 ----
    {
        const int idx = tid + 512;
        float4 t0 = sv[idx ^ 8],   t1 = sv[idx ^ 16],  t2 = sv[idx ^ 32];
        float4 t3 = sv[idx ^ 64],  t4 = sv[idx ^ 128], t5 = sv[idx ^ 256];
        add4(t0, t1); add4(t2, t3); add4(t4, t5);
        add4(t0, v0);                   // reg dir (bit 20)
        add4(t2, n1);                   // global dir (bit 21)
        add4(t0, t2); add4(t0, t4);
        o1.x = fmaf(c, t0.x, o1.x);
        o1.y = fmaf(c, t0.y, o1.y);
        o1.z = fmaf(c, t0.z, o1.z);
        o1.w = fmaf(c, t0.w, o1.w);
        o4[gG1] = o1;
    }
}

// ---------------------------------------------------------------------------
// Launch: tables -> K1 (bits 0..13 + diag, writes out)
//                -> K2 (bits 14..21, RMW out).
// ---------------------------------------------------------------------------
extern "C" void kernel_launch(void* const* d_in, const int* in_sizes, int n_in,
                              void* d_out, int out_size)
{
    const float* sr     = (const float*)d_in[0];
    const float* si     = (const float*)d_in[1];
    const float* rabi   = (const float*)d_in[2];
    const float* detune = (const float*)d_in[3];
    const float* U      = (const float*)d_in[4];
    float* out = (float*)d_out;

    cudaFuncSetAttribute(k1_low_kernel,
                         cudaFuncAttributeMaxDynamicSharedMemorySize, 65536);
    cudaFuncSetAttribute(k2_high_kernel,
                         cudaFuncAttributeMaxDynamicSharedMemorySize, 16384);

    tables_kernel<<<8, 256>>>(U, detune);
    k1_low_kernel<<<dim3(256, 2), 512, 65536>>>(sr, si, rabi, out);
    k2_high_kernel<<<dim3(1024, 2), 512, 16384>>>(sr, si, rabi, out);
}